// round 3
// baseline (speedup 1.0000x reference)
#include <cuda_runtime.h>

#define B_ 4
#define S_ 2048
#define H_ 8
#define D_ 64
#define C_ 64
#define NC_ (S_/C_)      // 32 chunks per (b,h)
#define BH_ (B_*H_)      // 32
#define SCALE 0.125f     // 1/sqrt(64)
#define THR 128

typedef unsigned long long ull;

// Per-(bh,chunk) 64x64 KV state scratch: 16 MB
__device__ float g_state[(size_t)BH_*NC_*D_*D_];

__device__ __forceinline__ float featf(float x) {
    return x > 0.f ? x + 1.f : __expf(x);   // elu(x)+1
}
__device__ __forceinline__ void fma2(ull& d, ull a, ull b) {
    asm("fma.rn.f32x2 %0, %1, %2, %0;" : "+l"(d) : "l"(a), "l"(b));
}
__device__ __forceinline__ void mul2(ull& d, ull a, ull b) {
    asm("mul.rn.f32x2 %0, %1, %2;" : "=l"(d) : "l"(a), "l"(b));
}
__device__ __forceinline__ ull pack2(float x) {
    ull r; asm("mov.b64 %0, {%1, %1};" : "=l"(r) : "f"(x)); return r;
}
__device__ __forceinline__ float2 unpack2(ull p) {
    float2 f; asm("mov.b64 {%0, %1}, %2;" : "=f"(f.x), "=f"(f.y) : "l"(p)); return f;
}

// acc[4] (4 e-pairs) += s * 8 contiguous floats (as 2 ulonglong2)
#define TILE_FMA(ACC, SP, V0, V1)                                        \
    do {                                                                  \
        fma2(ACC[0], SP, V0.x); fma2(ACC[1], SP, V0.y);                   \
        fma2(ACC[2], SP, V1.x); fma2(ACC[3], SP, V1.y);                   \
    } while (0)

// ---------------------------------------------------------------------------
// Kernel 1: per-chunk KV sums.  state[d][e] = sum_j k[j][d]*v[j][e]
// 128 threads: thread owns d-tile=4 (d0=(t>>3)*4) x e-tile=8 (e0=(t&7)*8).
// ---------------------------------------------------------------------------
__global__ void __launch_bounds__(THR) k_chunk_sum(const float* __restrict__ qk,
                                                   const float* __restrict__ v) {
    __shared__ float k_sh[C_ * 68];
    __shared__ float v_sh[C_ * 68];

    const int t  = threadIdx.x;
    const int bh = blockIdx.x / NC_;
    const int c  = blockIdx.x % NC_;
    const int b  = bh / H_, h = bh % H_;
    const int s0 = c * C_;

    #pragma unroll
    for (int r = 0; r < 8; r++) {
        int idx = t + r * THR;           // float4 index within 64x64 tile
        int j   = idx >> 4;
        int d4  = (idx & 15) << 2;
        size_t s = (size_t)(s0 + j);
        const float4 kf = *reinterpret_cast<const float4*>(
            qk + ((((size_t)b * S_ + s) * 2 + 1) * H_ + h) * D_ + d4);
        float4 kk;
        kk.x = featf(kf.x) * SCALE; kk.y = featf(kf.y) * SCALE;
        kk.z = featf(kf.z) * SCALE; kk.w = featf(kf.w) * SCALE;
        *reinterpret_cast<float4*>(&k_sh[j * 68 + d4]) = kk;
        const float4 vf = *reinterpret_cast<const float4*>(
            v + (((size_t)b * S_ + s) * H_ + h) * D_ + d4);
        *reinterpret_cast<float4*>(&v_sh[j * 68 + d4]) = vf;
    }
    __syncthreads();

    const int d0 = (t >> 3) << 2;
    const int e0 = (t & 7) << 3;

    ull acc[16];
    #pragma unroll
    for (int r = 0; r < 16; r++) acc[r] = 0ull;

    #pragma unroll 4
    for (int j = 0; j < C_; j++) {
        const float4 kf = *reinterpret_cast<const float4*>(&k_sh[j * 68 + d0]);
        const ulonglong2 V0 = *reinterpret_cast<const ulonglong2*>(&v_sh[j * 68 + e0]);
        const ulonglong2 V1 = *reinterpret_cast<const ulonglong2*>(&v_sh[j * 68 + e0 + 4]);
        ull k0 = pack2(kf.x), k1 = pack2(kf.y), k2 = pack2(kf.z), k3 = pack2(kf.w);
        TILE_FMA((acc + 0),  k0, V0, V1);
        TILE_FMA((acc + 4),  k1, V0, V1);
        TILE_FMA((acc + 8),  k2, V0, V1);
        TILE_FMA((acc + 12), k3, V0, V1);
    }

    float* base = g_state + (size_t)(bh * NC_ + c) * (D_ * D_);
    #pragma unroll
    for (int r = 0; r < 4; r++) {
        ulonglong2* dp = reinterpret_cast<ulonglong2*>(base + (d0 + r) * D_ + e0);
        dp[0] = make_ulonglong2(acc[r * 4 + 0], acc[r * 4 + 1]);
        dp[1] = make_ulonglong2(acc[r * 4 + 2], acc[r * 4 + 3]);
    }
}

// ---------------------------------------------------------------------------
// Kernel 2: exclusive prefix sum over chunks. One thread per state element.
// ---------------------------------------------------------------------------
__global__ void __launch_bounds__(256) k_prefix() {
    const int el  = blockIdx.x * 256 + threadIdx.x;
    const int bh  = el >> 12;
    const int off = el & 4095;
    float* p = g_state + (size_t)bh * NC_ * (D_ * D_) + off;
    float run = 0.f;
    #pragma unroll
    for (int c = 0; c < NC_; c++) {
        float tmp = p[(size_t)c * (D_ * D_)];
        p[(size_t)c * (D_ * D_)] = run;
        run += tmp;
    }
}

// ---------------------------------------------------------------------------
// Kernel 3: output. 128 threads: thread owns i-tile=4 x e-tile=8.
//   out[i][e] = norm_i * ( q_i @ state[:,e]  +  sum_{j<=i} (q_i.k_j) v[j][e] )
// ---------------------------------------------------------------------------
__global__ void __launch_bounds__(THR) k_output(const float* __restrict__ qk,
                                                const float* __restrict__ v,
                                                const float* __restrict__ nvec,
                                                const float* __restrict__ offset,
                                                float* __restrict__ out) {
    extern __shared__ float sm[];
    float* qT  = sm;                     // [64][68]  qT[d][i]
    float* kT  = qT + 64 * 68;           // [64][68]  kT[d][j]
    float* vS  = kT + 64 * 68;           // [64][68]  vS[j][e]
    float* stS = vS + 64 * 68;           // [64][68]  stS[d][e]
    float* A   = stS + 64 * 68;          // [64][65]  A[j][i]  (column-major)

    const int t  = threadIdx.x;
    const int bh = blockIdx.x / NC_;
    const int c  = blockIdx.x % NC_;
    const int b  = bh / H_, h = bh % H_;
    const int s0 = c * C_;

    const float* stg = g_state + (size_t)(bh * NC_ + c) * (D_ * D_);

    #pragma unroll
    for (int r = 0; r < 8; r++) {
        int idx = t + r * THR;
        int row = idx >> 4;
        int d4  = (idx & 15) << 2;
        size_t s = (size_t)(s0 + row);
        const float4 qf = *reinterpret_cast<const float4*>(
            qk + ((((size_t)b * S_ + s) * 2 + 0) * H_ + h) * D_ + d4);
        qT[(d4 + 0) * 68 + row] = featf(qf.x);
        qT[(d4 + 1) * 68 + row] = featf(qf.y);
        qT[(d4 + 2) * 68 + row] = featf(qf.z);
        qT[(d4 + 3) * 68 + row] = featf(qf.w);
        const float4 kf = *reinterpret_cast<const float4*>(
            qk + ((((size_t)b * S_ + s) * 2 + 1) * H_ + h) * D_ + d4);
        kT[(d4 + 0) * 68 + row] = featf(kf.x) * SCALE;
        kT[(d4 + 1) * 68 + row] = featf(kf.y) * SCALE;
        kT[(d4 + 2) * 68 + row] = featf(kf.z) * SCALE;
        kT[(d4 + 3) * 68 + row] = featf(kf.w) * SCALE;
        const float4 vf = *reinterpret_cast<const float4*>(
            v + (((size_t)b * S_ + s) * H_ + h) * D_ + d4);
        *reinterpret_cast<float4*>(&vS[row * 68 + d4]) = vf;
        const float4 sf = *reinterpret_cast<const float4*>(stg + row * D_ + d4);
        *reinterpret_cast<float4*>(&stS[row * 68 + d4]) = sf;
    }
    __syncthreads();

    const int i0 = (t >> 3) << 2;       // 4 i's
    const int e0 = (t & 7) << 3;        // 8 e's (also the j-group for A tile)

    ull o[16], a[16];
    #pragma unroll
    for (int r = 0; r < 16; r++) { o[r] = 0ull; a[r] = 0ull; }

    // Fused: o += q[i]*state[d][e],  a += q[i]*k[d][j=e-group]
    #pragma unroll 4
    for (int d = 0; d < 64; d++) {
        const float4 qf = *reinterpret_cast<const float4*>(&qT[d * 68 + i0]);
        const ulonglong2 S0 = *reinterpret_cast<const ulonglong2*>(&stS[d * 68 + e0]);
        const ulonglong2 S1 = *reinterpret_cast<const ulonglong2*>(&stS[d * 68 + e0 + 4]);
        const ulonglong2 K0 = *reinterpret_cast<const ulonglong2*>(&kT[d * 68 + e0]);
        const ulonglong2 K1 = *reinterpret_cast<const ulonglong2*>(&kT[d * 68 + e0 + 4]);
        ull q0 = pack2(qf.x), q1 = pack2(qf.y), q2 = pack2(qf.z), q3 = pack2(qf.w);
        TILE_FMA((o + 0),  q0, S0, S1);  TILE_FMA((a + 0),  q0, K0, K1);
        TILE_FMA((o + 4),  q1, S0, S1);  TILE_FMA((a + 4),  q1, K0, K1);
        TILE_FMA((o + 8),  q2, S0, S1);  TILE_FMA((a + 8),  q2, K0, K1);
        TILE_FMA((o + 12), q3, S0, S1);  TILE_FMA((a + 12), q3, K0, K1);
    }

    // Store A column-major with causal mask (j <= i)
    #pragma unroll
    for (int r = 0; r < 4; r++) {
        const int i = i0 + r;
        #pragma unroll
        for (int p = 0; p < 4; p++) {
            float2 f = unpack2(a[r * 4 + p]);
            int j = e0 + 2 * p;
            A[(j + 0) * 65 + i] = (j     <= i) ? f.x : 0.f;
            A[(j + 1) * 65 + i] = (j + 1 <= i) ? f.y : 0.f;
        }
    }
    __syncthreads();

    // o += A[:,i] @ v ; warp-uniform causal bound (warp covers i in [16w,16w+15])
    const int jmax = ((t >> 5) << 4) + 16;
    #pragma unroll 8
    for (int j = 0; j < jmax; j++) {
        const ulonglong2 V0 = *reinterpret_cast<const ulonglong2*>(&vS[j * 68 + e0]);
        const ulonglong2 V1 = *reinterpret_cast<const ulonglong2*>(&vS[j * 68 + e0 + 4]);
        ull a0 = pack2(A[j * 65 + i0 + 0]);
        ull a1 = pack2(A[j * 65 + i0 + 1]);
        ull a2 = pack2(A[j * 65 + i0 + 2]);
        ull a3 = pack2(A[j * 65 + i0 + 3]);
        TILE_FMA((o + 0),  a0, V0, V1);
        TILE_FMA((o + 4),  a1, V0, V1);
        TILE_FMA((o + 8),  a2, V0, V1);
        TILE_FMA((o + 12), a3, V0, V1);
    }

    // Epilogue: norm_i = sigmoid(-(n+off)); write 4 rows x 8 floats
    const float off = offset[h];
    #pragma unroll
    for (int r = 0; r < 4; r++) {
        const size_t s = (size_t)(s0 + i0 + r);
        float z    = nvec[((size_t)b * S_ + s) * H_ + h] + off;
        float norm = 1.f / (1.f + __expf(z));
        ull np = pack2(norm);
        #pragma unroll
        for (int p = 0; p < 4; p++) mul2(o[r * 4 + p], o[r * 4 + p], np);
        float* op = out + (((size_t)b * S_ + s) * H_ + h) * D_ + e0;
        ulonglong2* ov = reinterpret_cast<ulonglong2*>(op);
        ov[0] = make_ulonglong2(o[r * 4 + 0], o[r * 4 + 1]);
        ov[1] = make_ulonglong2(o[r * 4 + 2], o[r * 4 + 3]);
    }
}

// ---------------------------------------------------------------------------
extern "C" void kernel_launch(void* const* d_in, const int* in_sizes, int n_in,
                              void* d_out, int out_size) {
    (void)in_sizes; (void)n_in; (void)out_size;
    const float* qk     = (const float*)d_in[0];
    const float* v      = (const float*)d_in[1];
    const float* nvec   = (const float*)d_in[2];
    const float* offset = (const float*)d_in[3];
    float* out = (float*)d_out;

    const int smem3 = (64 * 68 * 4 + 64 * 65) * (int)sizeof(float);  // 86272 B
    cudaFuncSetAttribute(k_output, cudaFuncAttributeMaxDynamicSharedMemorySize, smem3);

    k_chunk_sum<<<BH_ * NC_, THR>>>(qk, v);
    k_prefix<<<512, 256>>>();
    k_output<<<BH_ * NC_, THR, smem3>>>(qk, v, nvec, offset, out);
}

// round 5
// speedup vs baseline: 1.6974x; 1.6974x over previous
#include <cuda_runtime.h>
#include <cstdint>

#define B_ 4
#define S_ 2048
#define H_ 8
#define D_ 64
#define C_ 64
#define NC_ (S_/C_)      // 32
#define BH_ (B_*H_)      // 32
#define SCALE 0.125f

// Per-(bh,chunk) 64x64 state scratch, state[d][e]: 16 MB
__device__ float g_state[(size_t)BH_*NC_*D_*D_];

__device__ __forceinline__ float featf(float x) {
    return x > 0.f ? x + 1.f : __expf(x);   // elu(x)+1
}
__device__ __forceinline__ uint32_t tf32r(float x) {
    uint32_t r; asm("cvt.rn.tf32.f32 %0, %1;" : "=r"(r) : "f"(x)); return r;
}

// D(16x8,f32) += A(16x8,tf32) @ B(8x8,tf32)   [m16n8k8 row.col]
#define MMA8(D, A0, A1, A2, A3, B0, B1)                                      \
    asm volatile("mma.sync.aligned.m16n8k8.row.col.f32.tf32.tf32.f32 "       \
        "{%0,%1,%2,%3}, {%4,%5,%6,%7}, {%8,%9}, {%0,%1,%2,%3};"              \
        : "+f"((D)[0]), "+f"((D)[1]), "+f"((D)[2]), "+f"((D)[3])             \
        : "r"(A0), "r"(A1), "r"(A2), "r"(A3), "r"(B0), "r"(B1))

// ---------------------------------------------------------------------------
// Kernel 1: state[d][e] = sum_j (k[j][d]*SCALE) * v[j][e]   (64x64x64 GEMM)
// 128 threads = 4 warps; warp w owns d-rows [16w, 16w+16).
// ---------------------------------------------------------------------------
__global__ void __launch_bounds__(128) k_chunk_sum(const float* __restrict__ qk,
                                                   const float* __restrict__ v) {
    extern __shared__ float sm[];
    float* kT = sm;                  // [64][65]  kT[d][j]  (tf32 bits)
    float* vS = kT + 64 * 65;        // [64][68]  v[j][e]   (tf32 bits)
    float* oS = vS + 64 * 68;        // [64][68]  staging (f32)
    uint32_t* kTu = reinterpret_cast<uint32_t*>(kT);
    uint32_t* vSu = reinterpret_cast<uint32_t*>(vS);

    const int t  = threadIdx.x;
    const int bh = blockIdx.x / NC_;
    const int c  = blockIdx.x % NC_;
    const int b  = bh / H_, h = bh % H_;
    const int s0 = c * C_;

    #pragma unroll
    for (int r = 0; r < 8; r++) {
        int idx = t + r * 128;           // float4 index in 64x64
        int j   = idx >> 4;
        int d4  = (idx & 15) << 2;
        size_t s = (size_t)(s0 + j);
        const float4 kf = *reinterpret_cast<const float4*>(
            qk + ((((size_t)b * S_ + s) * 2 + 1) * H_ + h) * D_ + d4);
        kTu[(d4 + 0) * 65 + j] = tf32r(featf(kf.x) * SCALE);
        kTu[(d4 + 1) * 65 + j] = tf32r(featf(kf.y) * SCALE);
        kTu[(d4 + 2) * 65 + j] = tf32r(featf(kf.z) * SCALE);
        kTu[(d4 + 3) * 65 + j] = tf32r(featf(kf.w) * SCALE);
        const float4 vf = *reinterpret_cast<const float4*>(
            v + (((size_t)b * S_ + s) * H_ + h) * D_ + d4);
        uint4 vu = make_uint4(tf32r(vf.x), tf32r(vf.y), tf32r(vf.z), tf32r(vf.w));
        *reinterpret_cast<uint4*>(&vSu[j * 68 + d4]) = vu;
    }
    __syncthreads();

    const int warp = t >> 5, lane = t & 31;
    const int g = lane >> 2, tq = lane & 3;
    const int d0w = warp * 16;

    float acc[8][4];
    #pragma unroll
    for (int n = 0; n < 8; n++)
        #pragma unroll
        for (int p = 0; p < 4; p++) acc[n][p] = 0.f;

    #pragma unroll
    for (int kt = 0; kt < 8; kt++) {
        const int j0 = kt * 8;
        uint32_t a0 = kTu[(d0w + g)     * 65 + j0 + tq];
        uint32_t a1 = kTu[(d0w + g + 8) * 65 + j0 + tq];
        uint32_t a2 = kTu[(d0w + g)     * 65 + j0 + tq + 4];
        uint32_t a3 = kTu[(d0w + g + 8) * 65 + j0 + tq + 4];
        #pragma unroll
        for (int nt = 0; nt < 8; nt++) {
            const int e0 = nt * 8;
            uint32_t b0 = vSu[(j0 + tq)     * 68 + e0 + g];
            uint32_t b1 = vSu[(j0 + tq + 4) * 68 + e0 + g];
            MMA8(acc[nt], a0, a1, a2, a3, b0, b1);
        }
    }

    // stage fragments then coalesced global store
    #pragma unroll
    for (int nt = 0; nt < 8; nt++) {
        const int e = nt * 8 + 2 * tq;
        oS[(d0w + g)     * 68 + e]     = acc[nt][0];
        oS[(d0w + g)     * 68 + e + 1] = acc[nt][1];
        oS[(d0w + g + 8) * 68 + e]     = acc[nt][2];
        oS[(d0w + g + 8) * 68 + e + 1] = acc[nt][3];
    }
    __syncthreads();

    float* base = g_state + (size_t)(bh * NC_ + c) * (D_ * D_);
    #pragma unroll
    for (int r = 0; r < 8; r++) {
        int idx = t + r * 128;
        int row = idx >> 4;
        int d4  = (idx & 15) << 2;
        *reinterpret_cast<float4*>(base + row * D_ + d4) =
            *reinterpret_cast<const float4*>(&oS[row * 68 + d4]);
    }
}

// ---------------------------------------------------------------------------
// Kernel 2: exclusive prefix over chunks.
// ---------------------------------------------------------------------------
__global__ void __launch_bounds__(256) k_prefix() {
    const int el  = blockIdx.x * 256 + threadIdx.x;
    const int bh  = el >> 12;
    const int off = el & 4095;
    float* p = g_state + (size_t)bh * NC_ * (D_ * D_) + off;
    float run = 0.f;
    #pragma unroll
    for (int c = 0; c < NC_; c++) {
        float tmp = p[(size_t)c * (D_ * D_)];
        p[(size_t)c * (D_ * D_)] = run;
        run += tmp;
    }
}

// ---------------------------------------------------------------------------
// Kernel 3: out[i][e] = norm_i * ( q@state + causal(q@k^T) @ v )
// 128 threads = 4 warps; warp w owns i-rows [16w, 16w+16).
// ---------------------------------------------------------------------------
__global__ void __launch_bounds__(128) k_output(const float* __restrict__ qk,
                                                const float* __restrict__ v,
                                                const float* __restrict__ nvec,
                                                const float* __restrict__ offset,
                                                float* __restrict__ out) {
    extern __shared__ float sm[];
    float* qS  = sm;                 // [64][68]  q[i][d]      (tf32 bits)
    float* kS  = qS  + 64 * 68;      // [64][68]  k[j][d]      (tf32 bits)
    float* vS  = kS  + 64 * 68;      // [64][68]  v[j][e]      (tf32 bits)
    float* stS = vS  + 64 * 68;      // [64][68]  state[d][e]  (tf32 bits)
    float* oS  = stS + 64 * 68;      // [64][68]  out staging  (f32)
    float* sS  = oS  + 64 * 68;      // [64][65]  scores[i][j] (tf32 bits)
    uint32_t* qSu  = reinterpret_cast<uint32_t*>(qS);
    uint32_t* kSu  = reinterpret_cast<uint32_t*>(kS);
    uint32_t* vSu  = reinterpret_cast<uint32_t*>(vS);
    uint32_t* stSu = reinterpret_cast<uint32_t*>(stS);
    uint32_t* sSu  = reinterpret_cast<uint32_t*>(sS);

    const int t  = threadIdx.x;
    const int bh = blockIdx.x / NC_;
    const int c  = blockIdx.x % NC_;
    const int b  = bh / H_, h = bh % H_;
    const int s0 = c * C_;

    const float* stg = g_state + (size_t)(bh * NC_ + c) * (D_ * D_);

    #pragma unroll
    for (int r = 0; r < 8; r++) {
        int idx = t + r * 128;
        int row = idx >> 4;
        int d4  = (idx & 15) << 2;
        size_t s = (size_t)(s0 + row);
        const float4 qf = *reinterpret_cast<const float4*>(
            qk + ((((size_t)b * S_ + s) * 2 + 0) * H_ + h) * D_ + d4);
        uint4 qu = make_uint4(tf32r(featf(qf.x)), tf32r(featf(qf.y)),
                              tf32r(featf(qf.z)), tf32r(featf(qf.w)));
        *reinterpret_cast<uint4*>(&qSu[row * 68 + d4]) = qu;
        const float4 kf = *reinterpret_cast<const float4*>(
            qk + ((((size_t)b * S_ + s) * 2 + 1) * H_ + h) * D_ + d4);
        uint4 ku = make_uint4(tf32r(featf(kf.x) * SCALE), tf32r(featf(kf.y) * SCALE),
                              tf32r(featf(kf.z) * SCALE), tf32r(featf(kf.w) * SCALE));
        *reinterpret_cast<uint4*>(&kSu[row * 68 + d4]) = ku;
        const float4 vf = *reinterpret_cast<const float4*>(
            v + (((size_t)b * S_ + s) * H_ + h) * D_ + d4);
        uint4 vu = make_uint4(tf32r(vf.x), tf32r(vf.y), tf32r(vf.z), tf32r(vf.w));
        *reinterpret_cast<uint4*>(&vSu[row * 68 + d4]) = vu;
        const float4 sf = *reinterpret_cast<const float4*>(stg + row * D_ + d4);
        uint4 su = make_uint4(tf32r(sf.x), tf32r(sf.y), tf32r(sf.z), tf32r(sf.w));
        *reinterpret_cast<uint4*>(&stSu[row * 68 + d4]) = su;
    }
    __syncthreads();

    const int warp = t >> 5, lane = t & 31;
    const int g = lane >> 2, tq = lane & 3;
    const int i0 = warp * 16;
    const int ntS = 2 * warp + 2;    // score tiles needed by this warp (causal)

    float dO[8][4];                  // out tiles over e
    float dS[8][4];                  // score tiles over j
    #pragma unroll
    for (int n = 0; n < 8; n++)
        #pragma unroll
        for (int p = 0; p < 4; p++) { dO[n][p] = 0.f; dS[n][p] = 0.f; }

    // Phase 1: fused  out1 = q @ state   and   scores = q @ k^T
    #pragma unroll
    for (int kt = 0; kt < 8; kt++) {
        const int d0 = kt * 8;
        uint32_t a0 = qSu[(i0 + g)     * 68 + d0 + tq];
        uint32_t a1 = qSu[(i0 + g + 8) * 68 + d0 + tq];
        uint32_t a2 = qSu[(i0 + g)     * 68 + d0 + tq + 4];
        uint32_t a3 = qSu[(i0 + g + 8) * 68 + d0 + tq + 4];
        #pragma unroll
        for (int nt = 0; nt < 8; nt++) {
            const int e0 = nt * 8;
            uint32_t b0 = stSu[(d0 + tq)     * 68 + e0 + g];
            uint32_t b1 = stSu[(d0 + tq + 4) * 68 + e0 + g];
            MMA8(dO[nt], a0, a1, a2, a3, b0, b1);
        }
        #pragma unroll
        for (int nt = 0; nt < 8; nt++) {
            if (nt >= ntS) break;                       // causal tile skip
            const int j0 = nt * 8;
            uint32_t b0 = kSu[(j0 + g) * 68 + d0 + tq];
            uint32_t b1 = kSu[(j0 + g) * 68 + d0 + tq + 4];
            MMA8(dS[nt], a0, a1, a2, a3, b0, b1);
        }
    }

    // Causal mask + store scores (same-warp rows -> no block sync needed)
    #pragma unroll
    for (int nt = 0; nt < 8; nt++) {
        if (nt >= ntS) break;
        const int j = nt * 8 + 2 * tq;
        const int iA = i0 + g, iB = i0 + g + 8;
        sSu[iA * 65 + j]     = tf32r((j     <= iA) ? dS[nt][0] : 0.f);
        sSu[iA * 65 + j + 1] = tf32r((j + 1 <= iA) ? dS[nt][1] : 0.f);
        sSu[iB * 65 + j]     = tf32r((j     <= iB) ? dS[nt][2] : 0.f);
        sSu[iB * 65 + j + 1] = tf32r((j + 1 <= iB) ? dS[nt][3] : 0.f);
    }
    __syncwarp();

    // Phase 2: out += scores @ v   (k-tiles limited by causality)
    #pragma unroll
    for (int kt = 0; kt < 8; kt++) {
        if (kt >= ntS) break;
        const int j0 = kt * 8;
        uint32_t a0 = sSu[(i0 + g)     * 65 + j0 + tq];
        uint32_t a1 = sSu[(i0 + g + 8) * 65 + j0 + tq];
        uint32_t a2 = sSu[(i0 + g)     * 65 + j0 + tq + 4];
        uint32_t a3 = sSu[(i0 + g + 8) * 65 + j0 + tq + 4];
        #pragma unroll
        for (int nt = 0; nt < 8; nt++) {
            const int e0 = nt * 8;
            uint32_t b0 = vSu[(j0 + tq)     * 68 + e0 + g];
            uint32_t b1 = vSu[(j0 + tq + 4) * 68 + e0 + g];
            MMA8(dO[nt], a0, a1, a2, a3, b0, b1);
        }
    }

    // Epilogue: norm scale, stage, coalesced store
    const float offh = offset[h];
    const int iA = i0 + g, iB = i0 + g + 8;
    float zA = nvec[((size_t)b * S_ + s0 + iA) * H_ + h] + offh;
    float zB = nvec[((size_t)b * S_ + s0 + iB) * H_ + h] + offh;
    float nA = 1.f / (1.f + __expf(zA));
    float nB = 1.f / (1.f + __expf(zB));
    #pragma unroll
    for (int nt = 0; nt < 8; nt++) {
        const int e = nt * 8 + 2 * tq;
        oS[iA * 68 + e]     = dO[nt][0] * nA;
        oS[iA * 68 + e + 1] = dO[nt][1] * nA;
        oS[iB * 68 + e]     = dO[nt][2] * nB;
        oS[iB * 68 + e + 1] = dO[nt][3] * nB;
    }
    __syncthreads();

    #pragma unroll
    for (int r = 0; r < 8; r++) {
        int idx = t + r * 128;
        int row = idx >> 4;
        int d4  = (idx & 15) << 2;
        float* op = out + (((size_t)b * S_ + s0 + row) * H_ + h) * D_ + d4;
        *reinterpret_cast<float4*>(op) = *reinterpret_cast<const float4*>(&oS[row * 68 + d4]);
    }
}

// ---------------------------------------------------------------------------
extern "C" void kernel_launch(void* const* d_in, const int* in_sizes, int n_in,
                              void* d_out, int out_size) {
    (void)in_sizes; (void)n_in; (void)out_size;
    const float* qk     = (const float*)d_in[0];
    const float* v      = (const float*)d_in[1];
    const float* nvec   = (const float*)d_in[2];
    const float* offset = (const float*)d_in[3];
    float* out = (float*)d_out;

    const int smem1 = (64 * 65 + 2 * 64 * 68) * (int)sizeof(float);       // 51456
    const int smem3 = (5 * 64 * 68 + 64 * 65) * (int)sizeof(float);       // 103680
    cudaFuncSetAttribute(k_chunk_sum, cudaFuncAttributeMaxDynamicSharedMemorySize, smem1);
    cudaFuncSetAttribute(k_output,    cudaFuncAttributeMaxDynamicSharedMemorySize, smem3);

    k_chunk_sum<<<BH_ * NC_, 128, smem1>>>(qk, v);
    k_prefix<<<512, 256>>>();
    k_output<<<BH_ * NC_, 128, smem3>>>(qk, v, nvec, offset, out);
}

// round 6
// speedup vs baseline: 2.0914x; 1.2321x over previous
#include <cuda_runtime.h>
#include <cstdint>

#define B_ 4
#define S_ 2048
#define H_ 8
#define D_ 64
#define C_ 64
#define NC_ (S_/C_)      // 32
#define BH_ (B_*H_)      // 32
#define SCALE 0.125f

// Per-(bh,chunk) 64x64 state scratch, state[d][e]: 16 MB
__device__ float g_state[(size_t)BH_*NC_*D_*D_];

__device__ __forceinline__ float featf(float x) {
    return x > 0.f ? x + 1.f : __expf(x);   // elu(x)+1
}
__device__ __forceinline__ uint32_t tf32r(float x) {
    uint32_t r; asm("cvt.rn.tf32.f32 %0, %1;" : "=r"(r) : "f"(x)); return r;
}
__device__ __forceinline__ uint32_t smem_u32(const void* p) {
    uint32_t a; asm("{ .reg .u64 t; cvta.to.shared.u64 t, %1; cvt.u32.u64 %0, t; }"
                    : "=r"(a) : "l"(p));
    return a;
}
__device__ __forceinline__ void cp16(uint32_t dst, const void* src) {
    asm volatile("cp.async.ca.shared.global [%0], [%1], 16;" :: "r"(dst), "l"(src));
}
#define CP_COMMIT() asm volatile("cp.async.commit_group;" ::: "memory")
#define CP_WAIT(n)  asm volatile("cp.async.wait_group %0;" :: "n"(n) : "memory")

// D(16x8,f32) += A(16x8,tf32) @ B(8x8,tf32)   [m16n8k8 row.col]
#define MMA8(D, A0, A1, A2, A3, B0, B1)                                      \
    asm volatile("mma.sync.aligned.m16n8k8.row.col.f32.tf32.tf32.f32 "       \
        "{%0,%1,%2,%3}, {%4,%5,%6,%7}, {%8,%9}, {%0,%1,%2,%3};"              \
        : "+f"((D)[0]), "+f"((D)[1]), "+f"((D)[2]), "+f"((D)[3])             \
        : "r"(A0), "r"(A1), "r"(A2), "r"(A3), "r"(B0), "r"(B1))

// ---------------------------------------------------------------------------
// Kernel 1: state[d][e] = sum_j (k[j][d]*SCALE) * v[j][e]
// smem: kT[64*65] | vS[64*68];  oS (staging) aliases base (dead after MMA).
// ---------------------------------------------------------------------------
__global__ void __launch_bounds__(128) k_chunk_sum(const float* __restrict__ qk,
                                                   const float* __restrict__ v) {
    extern __shared__ float sm[];
    float* kT = sm;                  // [64][65] kT[d][j] (tf32 bits)
    float* vS = kT + 64 * 65;        // [64][68] v[j][e]  (raw f32 bits)
    float* oS = sm;                  // aliases kT/vS after MMA
    uint32_t* kTu = reinterpret_cast<uint32_t*>(kT);
    uint32_t* vSu = reinterpret_cast<uint32_t*>(vS);
    const uint32_t smb = smem_u32(sm);

    const int t  = threadIdx.x;
    const int bh = blockIdx.x / NC_;
    const int c  = blockIdx.x % NC_;
    const int b  = bh / H_, h = bh % H_;
    const int s0 = c * C_;

    // async v loads first (no transform needed)
    #pragma unroll
    for (int r = 0; r < 8; r++) {
        int idx = t + r * 128;
        int j   = idx >> 4;
        int d4  = (idx & 15) << 2;
        cp16(smb + (uint32_t)(64 * 65 + j * 68 + d4) * 4,
             v + (((size_t)b * S_ + s0 + j) * H_ + h) * D_ + d4);
    }
    CP_COMMIT();

    // k transform (transposed store)
    #pragma unroll
    for (int r = 0; r < 8; r++) {
        int idx = t + r * 128;
        int j   = idx >> 4;
        int d4  = (idx & 15) << 2;
        const float4 kf = *reinterpret_cast<const float4*>(
            qk + ((((size_t)b * S_ + s0 + j) * 2 + 1) * H_ + h) * D_ + d4);
        kTu[(d4 + 0) * 65 + j] = tf32r(featf(kf.x) * SCALE);
        kTu[(d4 + 1) * 65 + j] = tf32r(featf(kf.y) * SCALE);
        kTu[(d4 + 2) * 65 + j] = tf32r(featf(kf.z) * SCALE);
        kTu[(d4 + 3) * 65 + j] = tf32r(featf(kf.w) * SCALE);
    }
    CP_WAIT(0);
    __syncthreads();

    const int warp = t >> 5, lane = t & 31;
    const int g = lane >> 2, tq = lane & 3;
    const int d0w = warp * 16;

    float acc[8][4];
    #pragma unroll
    for (int n = 0; n < 8; n++)
        #pragma unroll
        for (int p = 0; p < 4; p++) acc[n][p] = 0.f;

    #pragma unroll
    for (int kt = 0; kt < 8; kt++) {
        const int j0 = kt * 8;
        uint32_t a0 = kTu[(d0w + g)     * 65 + j0 + tq];
        uint32_t a1 = kTu[(d0w + g + 8) * 65 + j0 + tq];
        uint32_t a2 = kTu[(d0w + g)     * 65 + j0 + tq + 4];
        uint32_t a3 = kTu[(d0w + g + 8) * 65 + j0 + tq + 4];
        #pragma unroll
        for (int nt = 0; nt < 8; nt++) {
            const int e0 = nt * 8;
            uint32_t b0 = vSu[(j0 + tq)     * 68 + e0 + g];
            uint32_t b1 = vSu[(j0 + tq + 4) * 68 + e0 + g];
            MMA8(acc[nt], a0, a1, a2, a3, b0, b1);
        }
    }
    __syncthreads();   // kT/vS dead; oS aliases them

    #pragma unroll
    for (int nt = 0; nt < 8; nt++) {
        const int e = nt * 8 + 2 * tq;
        oS[(d0w + g)     * 68 + e]     = acc[nt][0];
        oS[(d0w + g)     * 68 + e + 1] = acc[nt][1];
        oS[(d0w + g + 8) * 68 + e]     = acc[nt][2];
        oS[(d0w + g + 8) * 68 + e + 1] = acc[nt][3];
    }
    __syncthreads();

    float* base = g_state + (size_t)(bh * NC_ + c) * (D_ * D_);
    #pragma unroll
    for (int r = 0; r < 8; r++) {
        int idx = t + r * 128;
        int row = idx >> 4;
        int d4  = (idx & 15) << 2;
        *reinterpret_cast<float4*>(base + row * D_ + d4) =
            *reinterpret_cast<const float4*>(&oS[row * 68 + d4]);
    }
}

// ---------------------------------------------------------------------------
// Kernel 2: exclusive prefix over chunks.
// ---------------------------------------------------------------------------
__global__ void __launch_bounds__(256) k_prefix() {
    const int el  = blockIdx.x * 256 + threadIdx.x;
    const int bh  = el >> 12;
    const int off = el & 4095;
    float* p = g_state + (size_t)bh * NC_ * (D_ * D_) + off;
    float run = 0.f;
    #pragma unroll
    for (int c = 0; c < NC_; c++) {
        float tmp = p[(size_t)c * (D_ * D_)];
        p[(size_t)c * (D_ * D_)] = run;
        run += tmp;
    }
}

// ---------------------------------------------------------------------------
// Kernel 3: out[i][e] = norm_i * ( q@state + causal(q@k^T) @ v )
// smem: qS | kS | vS | stS   (each [64][68])
//       sS (scores, [64][65]) aliases stS;  oS aliases qS.
// ---------------------------------------------------------------------------
__global__ void __launch_bounds__(128) k_output(const float* __restrict__ qk,
                                                const float* __restrict__ v,
                                                const float* __restrict__ nvec,
                                                const float* __restrict__ offset,
                                                float* __restrict__ out) {
    extern __shared__ float sm[];
    float* qS  = sm;                 // [64][68] q (tf32 bits); later: out staging
    float* kS  = qS + 64 * 68;       // [64][68] k (tf32 bits)
    float* vS  = kS + 64 * 68;       // [64][68] v (raw bits)
    float* stS = vS + 64 * 68;       // [64][68] state (raw bits); later: scores [64][65]
    float* oS  = qS;
    float* sS  = stS;
    uint32_t* qSu  = reinterpret_cast<uint32_t*>(qS);
    uint32_t* kSu  = reinterpret_cast<uint32_t*>(kS);
    uint32_t* vSu  = reinterpret_cast<uint32_t*>(vS);
    uint32_t* stSu = reinterpret_cast<uint32_t*>(stS);
    uint32_t* sSu  = reinterpret_cast<uint32_t*>(sS);
    const uint32_t smb = smem_u32(sm);

    const int t  = threadIdx.x;
    const int bh = blockIdx.x / NC_;
    const int c  = blockIdx.x % NC_;
    const int b  = bh / H_, h = bh % H_;
    const int s0 = c * C_;

    const float* stg = g_state + (size_t)(bh * NC_ + c) * (D_ * D_);

    // group 0: state; group 1: v
    #pragma unroll
    for (int r = 0; r < 8; r++) {
        int idx = t + r * 128;
        int row = idx >> 4;
        int d4  = (idx & 15) << 2;
        cp16(smb + (uint32_t)(3 * 64 * 68 + row * 68 + d4) * 4, stg + row * D_ + d4);
    }
    CP_COMMIT();
    #pragma unroll
    for (int r = 0; r < 8; r++) {
        int idx = t + r * 128;
        int row = idx >> 4;
        int d4  = (idx & 15) << 2;
        cp16(smb + (uint32_t)(2 * 64 * 68 + row * 68 + d4) * 4,
             v + (((size_t)b * S_ + s0 + row) * H_ + h) * D_ + d4);
    }
    CP_COMMIT();

    // q,k transforms
    #pragma unroll
    for (int r = 0; r < 8; r++) {
        int idx = t + r * 128;
        int row = idx >> 4;
        int d4  = (idx & 15) << 2;
        size_t s = (size_t)(s0 + row);
        const float4 qf = *reinterpret_cast<const float4*>(
            qk + ((((size_t)b * S_ + s) * 2 + 0) * H_ + h) * D_ + d4);
        uint4 qu = make_uint4(tf32r(featf(qf.x)), tf32r(featf(qf.y)),
                              tf32r(featf(qf.z)), tf32r(featf(qf.w)));
        *reinterpret_cast<uint4*>(&qSu[row * 68 + d4]) = qu;
        const float4 kf = *reinterpret_cast<const float4*>(
            qk + ((((size_t)b * S_ + s) * 2 + 1) * H_ + h) * D_ + d4);
        uint4 ku = make_uint4(tf32r(featf(kf.x) * SCALE), tf32r(featf(kf.y) * SCALE),
                              tf32r(featf(kf.z) * SCALE), tf32r(featf(kf.w) * SCALE));
        *reinterpret_cast<uint4*>(&kSu[row * 68 + d4]) = ku;
    }

    const int warp = t >> 5, lane = t & 31;
    const int g = lane >> 2, tq = lane & 3;
    const int i0 = warp * 16;
    const int ntS = 2 * warp + 2;

    // prefetch norm values
    const float offh = offset[h];
    const int iA = i0 + g, iB = i0 + g + 8;
    float zA = nvec[((size_t)b * S_ + s0 + iA) * H_ + h] + offh;
    float zB = nvec[((size_t)b * S_ + s0 + iB) * H_ + h] + offh;

    CP_WAIT(1);          // state landed (v may still be in flight)
    __syncthreads();

    float dO[8][4];
    float dS[8][4];
    #pragma unroll
    for (int n = 0; n < 8; n++)
        #pragma unroll
        for (int p = 0; p < 4; p++) { dO[n][p] = 0.f; dS[n][p] = 0.f; }

    // Phase 1: out1 = q @ state ; scores = q @ k^T (causal tiles only)
    #pragma unroll
    for (int kt = 0; kt < 8; kt++) {
        const int d0 = kt * 8;
        uint32_t a0 = qSu[(i0 + g)     * 68 + d0 + tq];
        uint32_t a1 = qSu[(i0 + g + 8) * 68 + d0 + tq];
        uint32_t a2 = qSu[(i0 + g)     * 68 + d0 + tq + 4];
        uint32_t a3 = qSu[(i0 + g + 8) * 68 + d0 + tq + 4];
        #pragma unroll
        for (int nt = 0; nt < 8; nt++) {
            const int e0 = nt * 8;
            uint32_t b0 = stSu[(d0 + tq)     * 68 + e0 + g];
            uint32_t b1 = stSu[(d0 + tq + 4) * 68 + e0 + g];
            MMA8(dO[nt], a0, a1, a2, a3, b0, b1);
        }
        #pragma unroll
        for (int nt = 0; nt < 8; nt++) {
            if (nt >= ntS) break;
            const int j0 = nt * 8;
            uint32_t b0 = kSu[(j0 + g) * 68 + d0 + tq];
            uint32_t b1 = kSu[(j0 + g) * 68 + d0 + tq + 4];
            MMA8(dS[nt], a0, a1, a2, a3, b0, b1);
        }
    }

    CP_WAIT(0);          // v landed
    __syncthreads();     // all warps done reading stS -> sS may overwrite it

    // Causal mask + store scores (own rows; cross-lane within warp)
    #pragma unroll
    for (int nt = 0; nt < 8; nt++) {
        if (nt >= ntS) break;
        const int j = nt * 8 + 2 * tq;
        sSu[iA * 65 + j]     = tf32r((j     <= iA) ? dS[nt][0] : 0.f);
        sSu[iA * 65 + j + 1] = tf32r((j + 1 <= iA) ? dS[nt][1] : 0.f);
        sSu[iB * 65 + j]     = tf32r((j     <= iB) ? dS[nt][2] : 0.f);
        sSu[iB * 65 + j + 1] = tf32r((j + 1 <= iB) ? dS[nt][3] : 0.f);
    }
    __syncwarp();

    // Phase 2: out += scores @ v
    #pragma unroll
    for (int kt = 0; kt < 8; kt++) {
        if (kt >= ntS) break;
        const int j0 = kt * 8;
        uint32_t a0 = sSu[(i0 + g)     * 65 + j0 + tq];
        uint32_t a1 = sSu[(i0 + g + 8) * 65 + j0 + tq];
        uint32_t a2 = sSu[(i0 + g)     * 65 + j0 + tq + 4];
        uint32_t a3 = sSu[(i0 + g + 8) * 65 + j0 + tq + 4];
        #pragma unroll
        for (int nt = 0; nt < 8; nt++) {
            const int e0 = nt * 8;
            uint32_t b0 = vSu[(j0 + tq)     * 68 + e0 + g];
            uint32_t b1 = vSu[(j0 + tq + 4) * 68 + e0 + g];
            MMA8(dO[nt], a0, a1, a2, a3, b0, b1);
        }
    }

    // Epilogue: norm scale, stage into oS (aliases qS: own rows only), store
    float nA = 1.f / (1.f + __expf(zA));
    float nB = 1.f / (1.f + __expf(zB));
    #pragma unroll
    for (int nt = 0; nt < 8; nt++) {
        const int e = nt * 8 + 2 * tq;
        oS[iA * 68 + e]     = dO[nt][0] * nA;
        oS[iA * 68 + e + 1] = dO[nt][1] * nA;
        oS[iB * 68 + e]     = dO[nt][2] * nB;
        oS[iB * 68 + e + 1] = dO[nt][3] * nB;
    }
    __syncthreads();

    #pragma unroll
    for (int r = 0; r < 8; r++) {
        int idx = t + r * 128;
        int row = idx >> 4;
        int d4  = (idx & 15) << 2;
        float* op = out + (((size_t)b * S_ + s0 + row) * H_ + h) * D_ + d4;
        *reinterpret_cast<float4*>(op) = *reinterpret_cast<const float4*>(&oS[row * 68 + d4]);
    }
}

// ---------------------------------------------------------------------------
extern "C" void kernel_launch(void* const* d_in, const int* in_sizes, int n_in,
                              void* d_out, int out_size) {
    (void)in_sizes; (void)n_in; (void)out_size;
    const float* qk     = (const float*)d_in[0];
    const float* v      = (const float*)d_in[1];
    const float* nvec   = (const float*)d_in[2];
    const float* offset = (const float*)d_in[3];
    float* out = (float*)d_out;

    const int smem1 = (64 * 65 + 64 * 68) * (int)sizeof(float);   // 34048
    const int smem3 = (4 * 64 * 68) * (int)sizeof(float);         // 69632
    cudaFuncSetAttribute(k_chunk_sum, cudaFuncAttributeMaxDynamicSharedMemorySize, smem1);
    cudaFuncSetAttribute(k_output,    cudaFuncAttributeMaxDynamicSharedMemorySize, smem3);

    k_chunk_sum<<<BH_ * NC_, 128, smem1>>>(qk, v);
    k_prefix<<<512, 256>>>();
    k_output<<<BH_ * NC_, 128, smem3>>>(qk, v, nvec, offset, out);
}

// round 7
// speedup vs baseline: 2.1429x; 1.0246x over previous
#include <cuda_runtime.h>
#include <cstdint>

#define B_ 4
#define S_ 2048
#define H_ 8
#define D_ 64
#define C_ 64
#define NC_ (S_/C_)      // 32
#define BH_ (B_*H_)      // 32
#define SCALE 0.125f

// Per-(bh,chunk) 64x64 state scratch, state[d][e]: 16 MB
__device__ float g_state[(size_t)BH_*NC_*D_*D_];

__device__ __forceinline__ float featf(float x) {
    return x > 0.f ? x + 1.f : __expf(x);   // elu(x)+1
}
__device__ __forceinline__ uint32_t tf32r(float x) {
    uint32_t r; asm("cvt.rn.tf32.f32 %0, %1;" : "=r"(r) : "f"(x)); return r;
}
__device__ __forceinline__ uint32_t smem_u32(const void* p) {
    uint32_t a; asm("{ .reg .u64 t; cvta.to.shared.u64 t, %1; cvt.u32.u64 %0, t; }"
                    : "=r"(a) : "l"(p));
    return a;
}
__device__ __forceinline__ void cp16(uint32_t dst, const void* src) {
    asm volatile("cp.async.ca.shared.global [%0], [%1], 16;" :: "r"(dst), "l"(src));
}
#define CP_COMMIT() asm volatile("cp.async.commit_group;" ::: "memory")
#define CP_WAIT(n)  asm volatile("cp.async.wait_group %0;" :: "n"(n) : "memory")

// D(16x8,f32) += A(16x8,tf32) @ B(8x8,tf32)   [m16n8k8 row.col]
#define MMA8(D, A0, A1, A2, A3, B0, B1)                                      \
    asm volatile("mma.sync.aligned.m16n8k8.row.col.f32.tf32.tf32.f32 "       \
        "{%0,%1,%2,%3}, {%4,%5,%6,%7}, {%8,%9}, {%0,%1,%2,%3};"              \
        : "+f"((D)[0]), "+f"((D)[1]), "+f"((D)[2]), "+f"((D)[3])             \
        : "r"(A0), "r"(A1), "r"(A2), "r"(A3), "r"(B0), "r"(B1))

// in-place RN tf32 conversion of a [64][68]-padded tile region (valid 64x64)
#define CVT_TILE(PTR, T)                                                     \
    do {                                                                      \
        _Pragma("unroll")                                                     \
        for (int _r = 0; _r < 4; _r++) {                                      \
            int _idx = (T) + _r * 256;                                        \
            int _row = _idx >> 4;                                             \
            int _d4  = (_idx & 15) << 2;                                      \
            float4 _f = *reinterpret_cast<const float4*>((PTR) + _row * 68 + _d4); \
            uint4 _u = make_uint4(tf32r(_f.x), tf32r(_f.y), tf32r(_f.z), tf32r(_f.w)); \
            *reinterpret_cast<uint4*>((PTR) + _row * 68 + _d4) = _u;          \
        }                                                                     \
    } while (0)

// ---------------------------------------------------------------------------
// Kernel 1: state[d][e] = sum_j (k[j][d]*SCALE) * v[j][e]
// 256 threads = 8 warps: warp = (d-block 0..3, e-half 0..1).
// ---------------------------------------------------------------------------
__global__ void __launch_bounds__(256) k_chunk_sum(const float* __restrict__ qk,
                                                   const float* __restrict__ v) {
    extern __shared__ float sm[];
    float* kT = sm;                  // [64][65] kT[d][j] (tf32 bits)
    float* vS = kT + 64 * 65;        // [64][68] v[j][e]
    float* oS = sm;                  // staging, aliases kT/vS after MMA
    uint32_t* kTu = reinterpret_cast<uint32_t*>(kT);
    uint32_t* vSu = reinterpret_cast<uint32_t*>(vS);
    const uint32_t smb = smem_u32(sm);

    const int t  = threadIdx.x;
    const int bh = blockIdx.x / NC_;
    const int c  = blockIdx.x % NC_;
    const int b  = bh / H_, h = bh % H_;
    const int s0 = c * C_;

    #pragma unroll
    for (int r = 0; r < 4; r++) {
        int idx = t + r * 256;
        int j   = idx >> 4;
        int d4  = (idx & 15) << 2;
        cp16(smb + (uint32_t)(64 * 65 + j * 68 + d4) * 4,
             v + (((size_t)b * S_ + s0 + j) * H_ + h) * D_ + d4);
    }
    CP_COMMIT();

    #pragma unroll
    for (int r = 0; r < 4; r++) {
        int idx = t + r * 256;
        int j   = idx >> 4;
        int d4  = (idx & 15) << 2;
        const float4 kf = *reinterpret_cast<const float4*>(
            qk + ((((size_t)b * S_ + s0 + j) * 2 + 1) * H_ + h) * D_ + d4);
        kTu[(d4 + 0) * 65 + j] = tf32r(featf(kf.x) * SCALE);
        kTu[(d4 + 1) * 65 + j] = tf32r(featf(kf.y) * SCALE);
        kTu[(d4 + 2) * 65 + j] = tf32r(featf(kf.z) * SCALE);
        kTu[(d4 + 3) * 65 + j] = tf32r(featf(kf.w) * SCALE);
    }
    CP_WAIT(0);
    __syncthreads();
    CVT_TILE(vS, t);            // RN-round v in place
    __syncthreads();

    const int warp = t >> 5, lane = t & 31;
    const int g = lane >> 2, tq = lane & 3;
    const int d0w = (warp >> 1) * 16;
    const int eh  = warp & 1;

    float acc[4][4];
    #pragma unroll
    for (int n = 0; n < 4; n++)
        #pragma unroll
        for (int p = 0; p < 4; p++) acc[n][p] = 0.f;

    #pragma unroll
    for (int kt = 0; kt < 8; kt++) {
        const int j0 = kt * 8;
        uint32_t a0 = kTu[(d0w + g)     * 65 + j0 + tq];
        uint32_t a1 = kTu[(d0w + g + 8) * 65 + j0 + tq];
        uint32_t a2 = kTu[(d0w + g)     * 65 + j0 + tq + 4];
        uint32_t a3 = kTu[(d0w + g + 8) * 65 + j0 + tq + 4];
        #pragma unroll
        for (int nt = 0; nt < 4; nt++) {
            const int e0 = (eh * 4 + nt) * 8;
            uint32_t b0 = vSu[(j0 + tq)     * 68 + e0 + g];
            uint32_t b1 = vSu[(j0 + tq + 4) * 68 + e0 + g];
            MMA8(acc[nt], a0, a1, a2, a3, b0, b1);
        }
    }
    __syncthreads();   // kT/vS dead; oS aliases them

    #pragma unroll
    for (int nt = 0; nt < 4; nt++) {
        const int e = (eh * 4 + nt) * 8 + 2 * tq;
        oS[(d0w + g)     * 68 + e]     = acc[nt][0];
        oS[(d0w + g)     * 68 + e + 1] = acc[nt][1];
        oS[(d0w + g + 8) * 68 + e]     = acc[nt][2];
        oS[(d0w + g + 8) * 68 + e + 1] = acc[nt][3];
    }
    __syncthreads();

    float* base = g_state + (size_t)(bh * NC_ + c) * (D_ * D_);
    #pragma unroll
    for (int r = 0; r < 4; r++) {
        int idx = t + r * 256;
        int row = idx >> 4;
        int d4  = (idx & 15) << 2;
        *reinterpret_cast<float4*>(base + row * D_ + d4) =
            *reinterpret_cast<const float4*>(&oS[row * 68 + d4]);
    }
}

// ---------------------------------------------------------------------------
// Kernel 2: exclusive prefix over chunks.
// ---------------------------------------------------------------------------
__global__ void __launch_bounds__(256) k_prefix() {
    const int el  = blockIdx.x * 256 + threadIdx.x;
    const int bh  = el >> 12;
    const int off = el & 4095;
    float* p = g_state + (size_t)bh * NC_ * (D_ * D_) + off;
    float run = 0.f;
    #pragma unroll
    for (int c = 0; c < NC_; c++) {
        float tmp = p[(size_t)c * (D_ * D_)];
        p[(size_t)c * (D_ * D_)] = run;
        run += tmp;
    }
}

// ---------------------------------------------------------------------------
// Kernel 3: out[i][e] = norm_i * ( q@state + causal(q@k^T) @ v )
// 256 threads = 8 warps: warp = (i-block ib 0..3, e-half eh 0..1).
// smem: qS | kS | vS | stS (each [64][68]); sS aliases stS; oS aliases qS.
// ---------------------------------------------------------------------------
__global__ void __launch_bounds__(256) k_output(const float* __restrict__ qk,
                                                const float* __restrict__ v,
                                                const float* __restrict__ nvec,
                                                const float* __restrict__ offset,
                                                float* __restrict__ out) {
    extern __shared__ float sm[];
    float* qS  = sm;                 // q (tf32 bits); later out staging
    float* kS  = qS + 64 * 68;
    float* vS  = kS + 64 * 68;
    float* stS = vS + 64 * 68;       // state; later scores [64][65]
    float* oS  = qS;
    float* sS  = stS;
    uint32_t* qSu  = reinterpret_cast<uint32_t*>(qS);
    uint32_t* kSu  = reinterpret_cast<uint32_t*>(kS);
    uint32_t* vSu  = reinterpret_cast<uint32_t*>(vS);
    uint32_t* stSu = reinterpret_cast<uint32_t*>(stS);
    uint32_t* sSu  = reinterpret_cast<uint32_t*>(sS);
    const uint32_t smb = smem_u32(sm);

    const int t  = threadIdx.x;
    const int bh = blockIdx.x / NC_;
    const int c  = blockIdx.x % NC_;
    const int b  = bh / H_, h = bh % H_;
    const int s0 = c * C_;

    const float* stg = g_state + (size_t)(bh * NC_ + c) * (D_ * D_);

    // group 0: state; group 1: v
    #pragma unroll
    for (int r = 0; r < 4; r++) {
        int idx = t + r * 256;
        int row = idx >> 4;
        int d4  = (idx & 15) << 2;
        cp16(smb + (uint32_t)(3 * 64 * 68 + row * 68 + d4) * 4, stg + row * D_ + d4);
    }
    CP_COMMIT();
    #pragma unroll
    for (int r = 0; r < 4; r++) {
        int idx = t + r * 256;
        int row = idx >> 4;
        int d4  = (idx & 15) << 2;
        cp16(smb + (uint32_t)(2 * 64 * 68 + row * 68 + d4) * 4,
             v + (((size_t)b * S_ + s0 + row) * H_ + h) * D_ + d4);
    }
    CP_COMMIT();

    // q,k transforms
    #pragma unroll
    for (int r = 0; r < 4; r++) {
        int idx = t + r * 256;
        int row = idx >> 4;
        int d4  = (idx & 15) << 2;
        size_t s = (size_t)(s0 + row);
        const float4 qf = *reinterpret_cast<const float4*>(
            qk + ((((size_t)b * S_ + s) * 2 + 0) * H_ + h) * D_ + d4);
        uint4 qu = make_uint4(tf32r(featf(qf.x)), tf32r(featf(qf.y)),
                              tf32r(featf(qf.z)), tf32r(featf(qf.w)));
        *reinterpret_cast<uint4*>(&qSu[row * 68 + d4]) = qu;
        const float4 kf = *reinterpret_cast<const float4*>(
            qk + ((((size_t)b * S_ + s) * 2 + 1) * H_ + h) * D_ + d4);
        uint4 ku = make_uint4(tf32r(featf(kf.x) * SCALE), tf32r(featf(kf.y) * SCALE),
                              tf32r(featf(kf.z) * SCALE), tf32r(featf(kf.w) * SCALE));
        *reinterpret_cast<uint4*>(&kSu[row * 68 + d4]) = ku;
    }

    const int warp = t >> 5, lane = t & 31;
    const int g = lane >> 2, tq = lane & 3;
    const int ib = warp >> 1;
    const int eh = warp & 1;
    const int i0 = ib * 16;
    const int ntS = 2 * ib + 2;      // causal j-tiles for this i-block

    const float offh = offset[h];
    const int iA = i0 + g, iB = i0 + g + 8;
    float zA = nvec[((size_t)b * S_ + s0 + iA) * H_ + h] + offh;
    float zB = nvec[((size_t)b * S_ + s0 + iB) * H_ + h] + offh;

    CP_WAIT(1);                // state landed
    __syncthreads();
    CVT_TILE(stS, t);          // RN-round state in place
    __syncthreads();

    float dO[4][4];
    float dS[4][4];
    #pragma unroll
    for (int n = 0; n < 4; n++)
        #pragma unroll
        for (int p = 0; p < 4; p++) { dO[n][p] = 0.f; dS[n][p] = 0.f; }

    // Phase 1: out1 = q @ state (own e-tiles); scores = q @ k^T (parity j-tiles)
    #pragma unroll
    for (int kt = 0; kt < 8; kt++) {
        const int d0 = kt * 8;
        uint32_t a0 = qSu[(i0 + g)     * 68 + d0 + tq];
        uint32_t a1 = qSu[(i0 + g + 8) * 68 + d0 + tq];
        uint32_t a2 = qSu[(i0 + g)     * 68 + d0 + tq + 4];
        uint32_t a3 = qSu[(i0 + g + 8) * 68 + d0 + tq + 4];
        #pragma unroll
        for (int nt = 0; nt < 4; nt++) {
            const int e0 = (eh * 4 + nt) * 8;
            uint32_t b0 = stSu[(d0 + tq)     * 68 + e0 + g];
            uint32_t b1 = stSu[(d0 + tq + 4) * 68 + e0 + g];
            MMA8(dO[nt], a0, a1, a2, a3, b0, b1);
        }
        #pragma unroll
        for (int nt2 = 0; nt2 < 4; nt2++) {
            const int jt = 2 * nt2 + eh;
            if (jt >= ntS) break;
            const int j0 = jt * 8;
            uint32_t b0 = kSu[(j0 + g) * 68 + d0 + tq];
            uint32_t b1 = kSu[(j0 + g) * 68 + d0 + tq + 4];
            MMA8(dS[nt2], a0, a1, a2, a3, b0, b1);
        }
    }

    CP_WAIT(0);                // v landed
    __syncthreads();           // all reads of stS done; sS may overwrite
    CVT_TILE(vS, t);           // RN-round v in place

    // Causal mask + store parity score tiles
    #pragma unroll
    for (int nt2 = 0; nt2 < 4; nt2++) {
        const int jt = 2 * nt2 + eh;
        if (jt >= ntS) break;
        const int j = jt * 8 + 2 * tq;
        sSu[iA * 65 + j]     = tf32r((j     <= iA) ? dS[nt2][0] : 0.f);
        sSu[iA * 65 + j + 1] = tf32r((j + 1 <= iA) ? dS[nt2][1] : 0.f);
        sSu[iB * 65 + j]     = tf32r((j     <= iB) ? dS[nt2][2] : 0.f);
        sSu[iB * 65 + j + 1] = tf32r((j + 1 <= iB) ? dS[nt2][3] : 0.f);
    }
    __syncthreads();           // scores + converted v visible to all

    // Phase 2: out += scores @ v (all causal j-tiles, own e-tiles)
    #pragma unroll
    for (int kt = 0; kt < 8; kt++) {
        if (kt >= ntS) break;
        const int j0 = kt * 8;
        uint32_t a0 = sSu[(i0 + g)     * 65 + j0 + tq];
        uint32_t a1 = sSu[(i0 + g + 8) * 65 + j0 + tq];
        uint32_t a2 = sSu[(i0 + g)     * 65 + j0 + tq + 4];
        uint32_t a3 = sSu[(i0 + g + 8) * 65 + j0 + tq + 4];
        #pragma unroll
        for (int nt = 0; nt < 4; nt++) {
            const int e0 = (eh * 4 + nt) * 8;
            uint32_t b0 = vSu[(j0 + tq)     * 68 + e0 + g];
            uint32_t b1 = vSu[(j0 + tq + 4) * 68 + e0 + g];
            MMA8(dO[nt], a0, a1, a2, a3, b0, b1);
        }
    }

    // Epilogue: norm scale, stage into oS (aliases qS), coalesced store
    float nA = 1.f / (1.f + __expf(zA));
    float nB = 1.f / (1.f + __expf(zB));
    __syncthreads();           // everyone done reading qS (phase 1)
    #pragma unroll
    for (int nt = 0; nt < 4; nt++) {
        const int e = (eh * 4 + nt) * 8 + 2 * tq;
        oS[iA * 68 + e]     = dO[nt][0] * nA;
        oS[iA * 68 + e + 1] = dO[nt][1] * nA;
        oS[iB * 68 + e]     = dO[nt][2] * nB;
        oS[iB * 68 + e + 1] = dO[nt][3] * nB;
    }
    __syncthreads();

    #pragma unroll
    for (int r = 0; r < 4; r++) {
        int idx = t + r * 256;
        int row = idx >> 4;
        int d4  = (idx & 15) << 2;
        float* op = out + (((size_t)b * S_ + s0 + row) * H_ + h) * D_ + d4;
        *reinterpret_cast<float4*>(op) = *reinterpret_cast<const float4*>(&oS[row * 68 + d4]);
    }
}

// ---------------------------------------------------------------------------
extern "C" void kernel_launch(void* const* d_in, const int* in_sizes, int n_in,
                              void* d_out, int out_size) {
    (void)in_sizes; (void)n_in; (void)out_size;
    const float* qk     = (const float*)d_in[0];
    const float* v      = (const float*)d_in[1];
    const float* nvec   = (const float*)d_in[2];
    const float* offset = (const float*)d_in[3];
    float* out = (float*)d_out;

    const int smem1 = (64 * 65 + 64 * 68) * (int)sizeof(float);   // 34048
    const int smem3 = (4 * 64 * 68) * (int)sizeof(float);         // 69632
    cudaFuncSetAttribute(k_chunk_sum, cudaFuncAttributeMaxDynamicSharedMemorySize, smem1);
    cudaFuncSetAttribute(k_output,    cudaFuncAttributeMaxDynamicSharedMemorySize, smem3);

    k_chunk_sum<<<BH_ * NC_, 256, smem1>>>(qk, v);
    k_prefix<<<512, 256>>>();
    k_output<<<BH_ * NC_, 256, smem3>>>(qk, v, nvec, offset, out);
}

// round 8
// speedup vs baseline: 2.3374x; 1.0907x over previous
#include <cuda_runtime.h>
#include <cstdint>

#define B_ 4
#define S_ 2048
#define H_ 8
#define D_ 64
#define C_ 64
#define NC_ (S_/C_)      // 32
#define BH_ (B_*H_)      // 32
#define SCALE 0.125f

// Per-(bh,chunk) 64x64 state scratch, state[d][e]: 16 MB
__device__ float g_state[(size_t)BH_*NC_*D_*D_];

__device__ __forceinline__ float featf(float x) {
    return x > 0.f ? x + 1.f : __expf(x);   // elu(x)+1
}
__device__ __forceinline__ uint32_t tf32r(float x) {
    uint32_t r; asm("cvt.rn.tf32.f32 %0, %1;" : "=r"(r) : "f"(x)); return r;
}
__device__ __forceinline__ uint32_t smem_u32(const void* p) {
    uint32_t a; asm("{ .reg .u64 t; cvta.to.shared.u64 t, %1; cvt.u32.u64 %0, t; }"
                    : "=r"(a) : "l"(p));
    return a;
}
__device__ __forceinline__ void cp16(uint32_t dst, const void* src) {
    asm volatile("cp.async.ca.shared.global [%0], [%1], 16;" :: "r"(dst), "l"(src));
}
#define CP_COMMIT() asm volatile("cp.async.commit_group;" ::: "memory")
#define CP_WAIT(n)  asm volatile("cp.async.wait_group %0;" :: "n"(n) : "memory")

// D(16x8,f32) += A(16x8,tf32) @ B(8x8,tf32)   [m16n8k8 row.col]
#define MMA8(D, A0, A1, A2, A3, B0, B1)                                      \
    asm volatile("mma.sync.aligned.m16n8k8.row.col.f32.tf32.tf32.f32 "       \
        "{%0,%1,%2,%3}, {%4,%5,%6,%7}, {%8,%9}, {%0,%1,%2,%3};"              \
        : "+f"((D)[0]), "+f"((D)[1]), "+f"((D)[2]), "+f"((D)[3])             \
        : "r"(A0), "r"(A1), "r"(A2), "r"(A3), "r"(B0), "r"(B1))

// ---------------------------------------------------------------------------
// Kernel 1: state[d][e] = sum_j (k[j][d]*SCALE) * v[j][e]
// 256 threads = 8 warps: warp = (d-block 0..3, e-half 0..1).
// One barrier; inline RN cvt on v; direct STG.64 of fragments.
// ---------------------------------------------------------------------------
__global__ void __launch_bounds__(256) k_chunk_sum(const float* __restrict__ qk,
                                                   const float* __restrict__ v) {
    extern __shared__ float sm[];
    float* kT = sm;                  // [64][65] kT[d][j] (tf32 bits)
    float* vS = kT + 64 * 65;        // [64][68] v[j][e]  (raw f32)
    uint32_t* kTu = reinterpret_cast<uint32_t*>(kT);
    const uint32_t smb = smem_u32(sm);

    const int t  = threadIdx.x;
    const int bh = blockIdx.x / NC_;
    const int c  = blockIdx.x % NC_;
    const int b  = bh / H_, h = bh % H_;
    const int s0 = c * C_;

    #pragma unroll
    for (int r = 0; r < 4; r++) {
        int idx = t + r * 256;
        int j   = idx >> 4;
        int d4  = (idx & 15) << 2;
        cp16(smb + (uint32_t)(64 * 65 + j * 68 + d4) * 4,
             v + (((size_t)b * S_ + s0 + j) * H_ + h) * D_ + d4);
    }
    CP_COMMIT();

    #pragma unroll
    for (int r = 0; r < 4; r++) {
        int idx = t + r * 256;
        int j   = idx >> 4;
        int d4  = (idx & 15) << 2;
        const float4 kf = *reinterpret_cast<const float4*>(
            qk + ((((size_t)b * S_ + s0 + j) * 2 + 1) * H_ + h) * D_ + d4);
        kTu[(d4 + 0) * 65 + j] = tf32r(featf(kf.x) * SCALE);
        kTu[(d4 + 1) * 65 + j] = tf32r(featf(kf.y) * SCALE);
        kTu[(d4 + 2) * 65 + j] = tf32r(featf(kf.z) * SCALE);
        kTu[(d4 + 3) * 65 + j] = tf32r(featf(kf.w) * SCALE);
    }
    CP_WAIT(0);
    __syncthreads();

    const int warp = t >> 5, lane = t & 31;
    const int g = lane >> 2, tq = lane & 3;
    const int d0w = (warp >> 1) * 16;
    const int eh  = warp & 1;

    float acc[4][4];
    #pragma unroll
    for (int n = 0; n < 4; n++)
        #pragma unroll
        for (int p = 0; p < 4; p++) acc[n][p] = 0.f;

    #pragma unroll
    for (int kt = 0; kt < 8; kt++) {
        const int j0 = kt * 8;
        uint32_t a0 = kTu[(d0w + g)     * 65 + j0 + tq];
        uint32_t a1 = kTu[(d0w + g + 8) * 65 + j0 + tq];
        uint32_t a2 = kTu[(d0w + g)     * 65 + j0 + tq + 4];
        uint32_t a3 = kTu[(d0w + g + 8) * 65 + j0 + tq + 4];
        #pragma unroll
        for (int nt = 0; nt < 4; nt++) {
            const int e0 = (eh * 4 + nt) * 8;
            uint32_t b0 = tf32r(vS[(j0 + tq)     * 68 + e0 + g]);
            uint32_t b1 = tf32r(vS[(j0 + tq + 4) * 68 + e0 + g]);
            MMA8(acc[nt], a0, a1, a2, a3, b0, b1);
        }
    }

    // direct fragment stores: each warp-op = 8 fully-used 32B sectors
    float* base = g_state + (size_t)(bh * NC_ + c) * (D_ * D_);
    #pragma unroll
    for (int nt = 0; nt < 4; nt++) {
        const int e = (eh * 4 + nt) * 8 + 2 * tq;
        *reinterpret_cast<float2*>(base + (d0w + g)     * D_ + e) =
            make_float2(acc[nt][0], acc[nt][1]);
        *reinterpret_cast<float2*>(base + (d0w + g + 8) * D_ + e) =
            make_float2(acc[nt][2], acc[nt][3]);
    }
}

// ---------------------------------------------------------------------------
// Kernel 2: exclusive prefix over chunks (float4 per thread).
// 32768 threads = BH_ * 1024 float4-lanes; grid 128 x 256.
// ---------------------------------------------------------------------------
__global__ void __launch_bounds__(256) k_prefix() {
    const int el  = blockIdx.x * 256 + threadIdx.x;   // float4 index
    const int bh  = el >> 10;
    const int off = (el & 1023) << 2;
    float* p = g_state + (size_t)bh * NC_ * (D_ * D_) + off;
    float4 run = make_float4(0.f, 0.f, 0.f, 0.f);
    #pragma unroll
    for (int c = 0; c < NC_; c++) {
        float4* q4 = reinterpret_cast<float4*>(p + (size_t)c * (D_ * D_));
        float4 tmp = *q4;
        *q4 = run;
        run.x += tmp.x; run.y += tmp.y; run.z += tmp.z; run.w += tmp.w;
    }
}

// ---------------------------------------------------------------------------
// Kernel 3: out[i][e] = norm_i * ( q@state + causal(q@k^T) @ v )
// 256 threads = 8 warps: warp = (i-block ib 0..3, e-half eh 0..1).
// smem: qS | kS | vS | stS (each [64][68]); sS aliases stS; oS aliases qS.
// Inline RN cvt on state/v B-loads (no CVT passes).
// ---------------------------------------------------------------------------
__global__ void __launch_bounds__(256) k_output(const float* __restrict__ qk,
                                                const float* __restrict__ v,
                                                const float* __restrict__ nvec,
                                                const float* __restrict__ offset,
                                                float* __restrict__ out) {
    extern __shared__ float sm[];
    float* qS  = sm;                 // q (tf32 bits); later out staging
    float* kS  = qS + 64 * 68;
    float* vS  = kS + 64 * 68;       // raw f32
    float* stS = vS + 64 * 68;       // raw f32; later scores [64][65]
    float* oS  = qS;
    float* sS  = stS;
    uint32_t* qSu = reinterpret_cast<uint32_t*>(qS);
    uint32_t* kSu = reinterpret_cast<uint32_t*>(kS);
    uint32_t* sSu = reinterpret_cast<uint32_t*>(sS);
    const uint32_t smb = smem_u32(sm);

    const int t  = threadIdx.x;
    const int bh = blockIdx.x / NC_;
    const int c  = blockIdx.x % NC_;
    const int b  = bh / H_, h = bh % H_;
    const int s0 = c * C_;

    const float* stg = g_state + (size_t)(bh * NC_ + c) * (D_ * D_);

    // group 0: state; group 1: v
    #pragma unroll
    for (int r = 0; r < 4; r++) {
        int idx = t + r * 256;
        int row = idx >> 4;
        int d4  = (idx & 15) << 2;
        cp16(smb + (uint32_t)(3 * 64 * 68 + row * 68 + d4) * 4, stg + row * D_ + d4);
    }
    CP_COMMIT();
    #pragma unroll
    for (int r = 0; r < 4; r++) {
        int idx = t + r * 256;
        int row = idx >> 4;
        int d4  = (idx & 15) << 2;
        cp16(smb + (uint32_t)(2 * 64 * 68 + row * 68 + d4) * 4,
             v + (((size_t)b * S_ + s0 + row) * H_ + h) * D_ + d4);
    }
    CP_COMMIT();

    // q,k transforms
    #pragma unroll
    for (int r = 0; r < 4; r++) {
        int idx = t + r * 256;
        int row = idx >> 4;
        int d4  = (idx & 15) << 2;
        size_t s = (size_t)(s0 + row);
        const float4 qf = *reinterpret_cast<const float4*>(
            qk + ((((size_t)b * S_ + s) * 2 + 0) * H_ + h) * D_ + d4);
        uint4 qu = make_uint4(tf32r(featf(qf.x)), tf32r(featf(qf.y)),
                              tf32r(featf(qf.z)), tf32r(featf(qf.w)));
        *reinterpret_cast<uint4*>(&qSu[row * 68 + d4]) = qu;
        const float4 kf = *reinterpret_cast<const float4*>(
            qk + ((((size_t)b * S_ + s) * 2 + 1) * H_ + h) * D_ + d4);
        uint4 ku = make_uint4(tf32r(featf(kf.x) * SCALE), tf32r(featf(kf.y) * SCALE),
                              tf32r(featf(kf.z) * SCALE), tf32r(featf(kf.w) * SCALE));
        *reinterpret_cast<uint4*>(&kSu[row * 68 + d4]) = ku;
    }

    const int warp = t >> 5, lane = t & 31;
    const int g = lane >> 2, tq = lane & 3;
    const int ib = warp >> 1;
    const int eh = warp & 1;
    const int i0 = ib * 16;
    const int ntS = 2 * ib + 2;      // causal j-tiles for this i-block

    const float offh = offset[h];
    const int iA = i0 + g, iB = i0 + g + 8;
    float zA = nvec[((size_t)b * S_ + s0 + iA) * H_ + h] + offh;
    float zB = nvec[((size_t)b * S_ + s0 + iB) * H_ + h] + offh;

    CP_WAIT(0);               // state + v landed
    __syncthreads();

    float dO[4][4];
    float dS[4][4];
    #pragma unroll
    for (int n = 0; n < 4; n++)
        #pragma unroll
        for (int p = 0; p < 4; p++) { dO[n][p] = 0.f; dS[n][p] = 0.f; }

    // Phase 1: out1 = q @ state (own e-tiles); scores = q @ k^T (parity j-tiles)
    #pragma unroll
    for (int kt = 0; kt < 8; kt++) {
        const int d0 = kt * 8;
        uint32_t a0 = qSu[(i0 + g)     * 68 + d0 + tq];
        uint32_t a1 = qSu[(i0 + g + 8) * 68 + d0 + tq];
        uint32_t a2 = qSu[(i0 + g)     * 68 + d0 + tq + 4];
        uint32_t a3 = qSu[(i0 + g + 8) * 68 + d0 + tq + 4];
        #pragma unroll
        for (int nt = 0; nt < 4; nt++) {
            const int e0 = (eh * 4 + nt) * 8;
            uint32_t b0 = tf32r(stS[(d0 + tq)     * 68 + e0 + g]);
            uint32_t b1 = tf32r(stS[(d0 + tq + 4) * 68 + e0 + g]);
            MMA8(dO[nt], a0, a1, a2, a3, b0, b1);
        }
        #pragma unroll
        for (int nt2 = 0; nt2 < 4; nt2++) {
            const int jt = 2 * nt2 + eh;
            if (jt >= ntS) break;
            const int j0 = jt * 8;
            uint32_t b0 = kSu[(j0 + g) * 68 + d0 + tq];
            uint32_t b1 = kSu[(j0 + g) * 68 + d0 + tq + 4];
            MMA8(dS[nt2], a0, a1, a2, a3, b0, b1);
        }
    }

    __syncthreads();           // all reads of stS done; sS may overwrite

    // Causal mask + store parity score tiles
    #pragma unroll
    for (int nt2 = 0; nt2 < 4; nt2++) {
        const int jt = 2 * nt2 + eh;
        if (jt >= ntS) break;
        const int j = jt * 8 + 2 * tq;
        sSu[iA * 65 + j]     = tf32r((j     <= iA) ? dS[nt2][0] : 0.f);
        sSu[iA * 65 + j + 1] = tf32r((j + 1 <= iA) ? dS[nt2][1] : 0.f);
        sSu[iB * 65 + j]     = tf32r((j     <= iB) ? dS[nt2][2] : 0.f);
        sSu[iB * 65 + j + 1] = tf32r((j + 1 <= iB) ? dS[nt2][3] : 0.f);
    }
    __syncthreads();           // scores visible to all

    // Phase 2: out += scores @ v (all causal j-tiles, own e-tiles)
    #pragma unroll
    for (int kt = 0; kt < 8; kt++) {
        if (kt >= ntS) break;
        const int j0 = kt * 8;
        uint32_t a0 = sSu[(i0 + g)     * 65 + j0 + tq];
        uint32_t a1 = sSu[(i0 + g + 8) * 65 + j0 + tq];
        uint32_t a2 = sSu[(i0 + g)     * 65 + j0 + tq + 4];
        uint32_t a3 = sSu[(i0 + g + 8) * 65 + j0 + tq + 4];
        #pragma unroll
        for (int nt = 0; nt < 4; nt++) {
            const int e0 = (eh * 4 + nt) * 8;
            uint32_t b0 = tf32r(vS[(j0 + tq)     * 68 + e0 + g]);
            uint32_t b1 = tf32r(vS[(j0 + tq + 4) * 68 + e0 + g]);
            MMA8(dO[nt], a0, a1, a2, a3, b0, b1);
        }
    }

    // Epilogue: norm scale, stage into oS (aliases qS), coalesced store
    float nA = 1.f / (1.f + __expf(zA));
    float nB = 1.f / (1.f + __expf(zB));
    __syncthreads();           // everyone done reading qS (phase 1)
    #pragma unroll
    for (int nt = 0; nt < 4; nt++) {
        const int e = (eh * 4 + nt) * 8 + 2 * tq;
        oS[iA * 68 + e]     = dO[nt][0] * nA;
        oS[iA * 68 + e + 1] = dO[nt][1] * nA;
        oS[iB * 68 + e]     = dO[nt][2] * nB;
        oS[iB * 68 + e + 1] = dO[nt][3] * nB;
    }
    __syncthreads();

    #pragma unroll
    for (int r = 0; r < 4; r++) {
        int idx = t + r * 256;
        int row = idx >> 4;
        int d4  = (idx & 15) << 2;
        float* op = out + (((size_t)b * S_ + s0 + row) * H_ + h) * D_ + d4;
        *reinterpret_cast<float4*>(op) = *reinterpret_cast<const float4*>(&oS[row * 68 + d4]);
    }
}

// ---------------------------------------------------------------------------
extern "C" void kernel_launch(void* const* d_in, const int* in_sizes, int n_in,
                              void* d_out, int out_size) {
    (void)in_sizes; (void)n_in; (void)out_size;
    const float* qk     = (const float*)d_in[0];
    const float* v      = (const float*)d_in[1];
    const float* nvec   = (const float*)d_in[2];
    const float* offset = (const float*)d_in[3];
    float* out = (float*)d_out;

    const int smem1 = (64 * 65 + 64 * 68) * (int)sizeof(float);   // 34048
    const int smem3 = (4 * 64 * 68) * (int)sizeof(float);         // 69632
    cudaFuncSetAttribute(k_chunk_sum, cudaFuncAttributeMaxDynamicSharedMemorySize, smem1);
    cudaFuncSetAttribute(k_output,    cudaFuncAttributeMaxDynamicSharedMemorySize, smem3);

    k_chunk_sum<<<BH_ * NC_, 256, smem1>>>(qk, v);
    k_prefix<<<128, 256>>>();
    k_output<<<BH_ * NC_, 256, smem3>>>(qk, v, nvec, offset, out);
}